// round 1
// baseline (speedup 1.0000x reference)
#include <cuda_runtime.h>
#include <math.h>

#define BT      8192          // B*T tokens
#define D_DIM   1024
#define E_NUM   8
#define H_DIM   4096
#define CAP     (2*BT)        // worst-case assignments per expert
#define NSLOT   (2*BT)        // total assignment slots (2 per token)

// ---------------- device scratch (no allocations allowed) ----------------
__device__ float g_h[(size_t)NSLOT * H_DIM];     // 256 MB: hidden activations per slot
__device__ float g_o[(size_t)NSLOT * D_DIM];     // 64 MB: expert outputs per slot
__device__ int   g_slots[E_NUM * CAP];           // per-expert slot lists
__device__ float g_gp[NSLOT];                    // gate prob per slot (2t=top1, 2t+1=top2)
__device__ int   g_cnt[E_NUM];
__device__ float g_imp[E_NUM];
__device__ int   g_loadc[E_NUM];

// ---------------- init ----------------
__global__ void init_kernel() {
    int i = threadIdx.x;
    if (i < E_NUM) { g_cnt[i] = 0; g_imp[i] = 0.f; g_loadc[i] = 0; }
}

// ---------------- router: logits, softmax, top2, lists, aux stats ----------------
__global__ void __launch_bounds__(256) router_kernel(const float* __restrict__ x,
                                                     const float* __restrict__ gW) {
    __shared__ float sW[E_NUM][D_DIM];   // 32 KB, transposed for conflict-free reads
    __shared__ float s_imp[E_NUM];
    __shared__ int   s_load[E_NUM];
    int tid = threadIdx.x;
    if (tid < E_NUM) { s_imp[tid] = 0.f; s_load[tid] = 0; }
    for (int i = tid; i < D_DIM * E_NUM; i += 256) {
        int d = i / E_NUM, e = i % E_NUM;
        sW[e][d] = gW[i];
    }
    __syncthreads();

    int warp = tid >> 5, lane = tid & 31;
    int t = blockIdx.x * 8 + warp;
    const float* xr = x + (size_t)t * D_DIM;

    float acc[E_NUM];
#pragma unroll
    for (int e = 0; e < E_NUM; e++) acc[e] = 0.f;
    for (int d = lane; d < D_DIM; d += 32) {
        float xv = xr[d];
#pragma unroll
        for (int e = 0; e < E_NUM; e++) acc[e] = fmaf(xv, sW[e][d], acc[e]);
    }
#pragma unroll
    for (int off = 16; off > 0; off >>= 1) {
#pragma unroll
        for (int e = 0; e < E_NUM; e++)
            acc[e] += __shfl_xor_sync(0xffffffffu, acc[e], off);
    }

    if (lane == 0) {
        float mx = acc[0];
#pragma unroll
        for (int e = 1; e < E_NUM; e++) mx = fmaxf(mx, acc[e]);
        float p[E_NUM], s = 0.f;
#pragma unroll
        for (int e = 0; e < E_NUM; e++) { p[e] = expf(acc[e] - mx); s += p[e]; }
        float inv = 1.f / s;
#pragma unroll
        for (int e = 0; e < E_NUM; e++) p[e] *= inv;

        int e1 = 0; float v1 = p[0];
#pragma unroll
        for (int e = 1; e < E_NUM; e++) if (p[e] > v1) { v1 = p[e]; e1 = e; }
        int e2 = -1; float v2 = -1.f;
#pragma unroll
        for (int e = 0; e < E_NUM; e++) if (e != e1 && p[e] > v2) { v2 = p[e]; e2 = e; }

        float ginv = 1.f / (v1 + v2);
        g_gp[2 * t]     = v1 * ginv;
        g_gp[2 * t + 1] = v2 * ginv;

        int p1 = atomicAdd(&g_cnt[e1], 1); g_slots[e1 * CAP + p1] = 2 * t;
        int p2 = atomicAdd(&g_cnt[e2], 1); g_slots[e2 * CAP + p2] = 2 * t + 1;
#pragma unroll
        for (int e = 0; e < E_NUM; e++) atomicAdd(&s_imp[e], p[e]);
        atomicAdd(&s_load[e1], 1);
    }
    __syncthreads();
    if (tid < E_NUM) {
        atomicAdd(&g_imp[tid], s_imp[tid]);
        atomicAdd(&g_loadc[tid], s_load[tid]);
    }
}

// ---------------- grouped GEMM ----------------
// PHASE1: A = gathered x rows (K=D), C = g_h (N=H), bias=b1, ReLU
// PHASE2: A = g_h slot rows (K=H), C = g_o (N=D), bias=b2
template <int N_SIZE, int K_SIZE, bool PHASE1>
__global__ void __launch_bounds__(256) gemm_kernel(const float* __restrict__ xin,
                                                   const float* __restrict__ W,
                                                   const float* __restrict__ bias) {
    int e  = blockIdx.z;
    int cnt = g_cnt[e];
    int m0 = blockIdx.y * 128;
    if (m0 >= cnt) return;
    int n0 = blockIdx.x * 128;

    __shared__ float As[8][128];
    __shared__ float Bs[8][128];
    __shared__ int   sSlot[128];

    int tid = threadIdx.x;
    if (tid < 128) {
        int m = m0 + tid;
        sSlot[tid] = (m < cnt) ? g_slots[e * CAP + m] : -1;
    }
    __syncthreads();

    // A-load mapping: 2 threads per row, float4 over k
    int rowA = tid >> 1;
    int kofs = (tid & 1) * 4;
    int slotA = sSlot[rowA];
    const float* aptr = nullptr;
    if (slotA >= 0) {
        if (PHASE1) aptr = xin + (size_t)(slotA >> 1) * K_SIZE + kofs;
        else        aptr = g_h + (size_t)slotA * K_SIZE + kofs;
    }
    // B-load mapping: 8 rows x 128 cols, float4 over n
    int krowB = tid >> 5;
    int ncolB = (tid & 31) * 4;
    const float* bptr = W + (size_t)e * K_SIZE * N_SIZE + (size_t)krowB * N_SIZE + n0 + ncolB;

    int tm = (tid >> 4) * 8;
    int tn = (tid & 15) * 8;

    float acc[8][8];
#pragma unroll
    for (int i = 0; i < 8; i++)
#pragma unroll
        for (int j = 0; j < 8; j++) acc[i][j] = 0.f;

    for (int kt = 0; kt < K_SIZE; kt += 8) {
        float4 av = make_float4(0.f, 0.f, 0.f, 0.f);
        if (aptr) av = *(const float4*)(aptr + kt);
        float4 bv = *(const float4*)(bptr + (size_t)kt * N_SIZE);
        __syncthreads();
        As[kofs + 0][rowA] = av.x;
        As[kofs + 1][rowA] = av.y;
        As[kofs + 2][rowA] = av.z;
        As[kofs + 3][rowA] = av.w;
        *(float4*)&Bs[krowB][ncolB] = bv;
        __syncthreads();
#pragma unroll
        for (int kk = 0; kk < 8; kk++) {
            float ra[8], rb[8];
            *(float4*)&ra[0] = *(const float4*)&As[kk][tm];
            *(float4*)&ra[4] = *(const float4*)&As[kk][tm + 4];
            *(float4*)&rb[0] = *(const float4*)&Bs[kk][tn];
            *(float4*)&rb[4] = *(const float4*)&Bs[kk][tn + 4];
#pragma unroll
            for (int i = 0; i < 8; i++)
#pragma unroll
                for (int j = 0; j < 8; j++)
                    acc[i][j] = fmaf(ra[i], rb[j], acc[i][j]);
        }
    }

    // epilogue
    float4 bv0 = *(const float4*)(bias + (size_t)e * N_SIZE + n0 + tn);
    float4 bv1 = *(const float4*)(bias + (size_t)e * N_SIZE + n0 + tn + 4);
    float bcol[8] = {bv0.x, bv0.y, bv0.z, bv0.w, bv1.x, bv1.y, bv1.z, bv1.w};
#pragma unroll
    for (int i = 0; i < 8; i++) {
        int m = m0 + tm + i;
        if (m >= cnt) continue;
        int slot = sSlot[tm + i];
        float* crow = (PHASE1 ? g_h : g_o) + (size_t)slot * N_SIZE + n0 + tn;
        float4 o0, o1;
        float v[8];
#pragma unroll
        for (int j = 0; j < 8; j++) {
            float t = acc[i][j] + bcol[j];
            if (PHASE1) t = fmaxf(t, 0.f);
            v[j] = t;
        }
        o0 = make_float4(v[0], v[1], v[2], v[3]);
        o1 = make_float4(v[4], v[5], v[6], v[7]);
        *(float4*)(crow)     = o0;
        *(float4*)(crow + 4) = o1;
    }
}

// ---------------- combine + aux ----------------
__global__ void combine_kernel(float* __restrict__ y, long long out_size) {
    long long idx = (long long)blockIdx.x * blockDim.x + threadIdx.x;
    const long long BTD = (long long)BT * D_DIM;
    if (idx < BTD) {
        long long t = idx / D_DIM;
        long long d = idx - t * D_DIM;
        float r = g_gp[2 * t]     * g_o[(size_t)(2 * t) * D_DIM + d]
                + g_gp[2 * t + 1] * g_o[(size_t)(2 * t + 1) * D_DIM + d];
        y[idx] = r;
    } else if (idx < out_size) {
        float aux = 0.f;
        const float invBT = 1.f / (float)BT;
#pragma unroll
        for (int e = 0; e < E_NUM; e++)
            aux += (g_imp[e] * invBT) * ((float)g_loadc[e] * invBT);
        aux *= (float)E_NUM * 0.01f;
        y[idx] = aux;
    }
}

// ---------------- launch ----------------
extern "C" void kernel_launch(void* const* d_in, const int* in_sizes, int n_in,
                              void* d_out, int out_size) {
    const float* x  = (const float*)d_in[0];
    const float* gW = (const float*)d_in[1];
    const float* w1 = (const float*)d_in[2];
    const float* b1 = (const float*)d_in[3];
    const float* w2 = (const float*)d_in[4];
    const float* b2 = (const float*)d_in[5];
    float* out = (float*)d_out;

    init_kernel<<<1, 32>>>();
    router_kernel<<<BT / 8, 256>>>(x, gW);

    dim3 g1(H_DIM / 128, CAP / 128, E_NUM);   // (32, 128, 8), most m-tiles exit early
    gemm_kernel<H_DIM, D_DIM, true><<<g1, 256>>>(x, w1, b1);

    dim3 g2(D_DIM / 128, CAP / 128, E_NUM);   // (8, 128, 8)
    gemm_kernel<D_DIM, H_DIM, false><<<g2, 256>>>(x, w2, b2);

    long long total = out_size;
    int blocks = (int)((total + 255) / 256);
    combine_kernel<<<blocks, 256>>>(out, total);
}

// round 3
// speedup vs baseline: 2.6042x; 2.6042x over previous
#include <cuda_runtime.h>
#include <cuda_bf16.h>
#include <math.h>
#include <stdint.h>

#define BT      8192
#define D_DIM   1024
#define E_NUM   8
#define H_DIM   4096
#define CAP     (2*BT)
#define NSLOT   (2*BT)

// ---------------- device scratch ----------------
__device__ __nv_bfloat16 g_x_hi[(size_t)BT * D_DIM];
__device__ __nv_bfloat16 g_x_lo[(size_t)BT * D_DIM];
__device__ __nv_bfloat16 g_w1t_hi[(size_t)E_NUM * H_DIM * D_DIM];
__device__ __nv_bfloat16 g_w1t_lo[(size_t)E_NUM * H_DIM * D_DIM];
__device__ __nv_bfloat16 g_w2t_hi[(size_t)E_NUM * D_DIM * H_DIM];
__device__ __nv_bfloat16 g_w2t_lo[(size_t)E_NUM * D_DIM * H_DIM];
__device__ __nv_bfloat16 g_h_hi[(size_t)NSLOT * H_DIM];
__device__ __nv_bfloat16 g_h_lo[(size_t)NSLOT * H_DIM];
__device__ float g_o[(size_t)NSLOT * D_DIM];
__device__ int   g_slots[E_NUM * CAP];
__device__ float g_gp[NSLOT];
__device__ int   g_cnt[E_NUM];
__device__ float g_imp[E_NUM];
__device__ int   g_loadc[E_NUM];

// ---------------- PTX helpers ----------------
__device__ __forceinline__ uint32_t smem_u32(const void* p) {
    return (uint32_t)__cvta_generic_to_shared(p);
}
__device__ __forceinline__ void cp_async16(uint32_t dst, const void* src) {
    asm volatile("cp.async.cg.shared.global [%0], [%1], 16;" :: "r"(dst), "l"(src));
}
#define CP_COMMIT() asm volatile("cp.async.commit_group;" ::: "memory")
#define CP_WAIT1()  asm volatile("cp.async.wait_group 1;" ::: "memory")

__device__ __forceinline__ void ldmatrix_x4(uint32_t* r, uint32_t addr) {
    asm volatile("ldmatrix.sync.aligned.m8n8.x4.shared.b16 {%0,%1,%2,%3}, [%4];"
        : "=r"(r[0]), "=r"(r[1]), "=r"(r[2]), "=r"(r[3]) : "r"(addr));
}
__device__ __forceinline__ void mma_16816(float* d, const uint32_t* a,
                                          uint32_t b0, uint32_t b1) {
    asm volatile(
        "mma.sync.aligned.m16n8k16.row.col.f32.bf16.bf16.f32 "
        "{%0,%1,%2,%3}, {%4,%5,%6,%7}, {%8,%9}, {%0,%1,%2,%3};"
        : "+f"(d[0]), "+f"(d[1]), "+f"(d[2]), "+f"(d[3])
        : "r"(a[0]), "r"(a[1]), "r"(a[2]), "r"(a[3]), "r"(b0), "r"(b1));
}

// ---------------- init ----------------
__global__ void init_kernel() {
    int i = threadIdx.x;
    if (i < E_NUM) { g_cnt[i] = 0; g_imp[i] = 0.f; g_loadc[i] = 0; }
}

// ---------------- router ----------------
__global__ void __launch_bounds__(256) router_kernel(const float* __restrict__ x,
                                                     const float* __restrict__ gW) {
    __shared__ float sW[E_NUM][D_DIM];
    __shared__ float s_imp[E_NUM];
    __shared__ int   s_load[E_NUM];
    int tid = threadIdx.x;
    if (tid < E_NUM) { s_imp[tid] = 0.f; s_load[tid] = 0; }
    for (int i = tid; i < D_DIM * E_NUM; i += 256) {
        int d = i / E_NUM, e = i % E_NUM;
        sW[e][d] = gW[i];
    }
    __syncthreads();

    int warp = tid >> 5, lane = tid & 31;
    int t = blockIdx.x * 8 + warp;
    const float* xr = x + (size_t)t * D_DIM;

    float acc[E_NUM];
#pragma unroll
    for (int e = 0; e < E_NUM; e++) acc[e] = 0.f;
    for (int d = lane; d < D_DIM; d += 32) {
        float xv = xr[d];
#pragma unroll
        for (int e = 0; e < E_NUM; e++) acc[e] = fmaf(xv, sW[e][d], acc[e]);
    }
#pragma unroll
    for (int off = 16; off > 0; off >>= 1) {
#pragma unroll
        for (int e = 0; e < E_NUM; e++)
            acc[e] += __shfl_xor_sync(0xffffffffu, acc[e], off);
    }

    if (lane == 0) {
        float mx = acc[0];
#pragma unroll
        for (int e = 1; e < E_NUM; e++) mx = fmaxf(mx, acc[e]);
        float p[E_NUM], s = 0.f;
#pragma unroll
        for (int e = 0; e < E_NUM; e++) { p[e] = expf(acc[e] - mx); s += p[e]; }
        float inv = 1.f / s;
#pragma unroll
        for (int e = 0; e < E_NUM; e++) p[e] *= inv;

        int e1 = 0; float v1 = p[0];
#pragma unroll
        for (int e = 1; e < E_NUM; e++) if (p[e] > v1) { v1 = p[e]; e1 = e; }
        int e2 = -1; float v2 = -1.f;
#pragma unroll
        for (int e = 0; e < E_NUM; e++) if (e != e1 && p[e] > v2) { v2 = p[e]; e2 = e; }

        float ginv = 1.f / (v1 + v2);
        g_gp[2 * t]     = v1 * ginv;
        g_gp[2 * t + 1] = v2 * ginv;

        int p1 = atomicAdd(&g_cnt[e1], 1); g_slots[e1 * CAP + p1] = 2 * t;
        int p2 = atomicAdd(&g_cnt[e2], 1); g_slots[e2 * CAP + p2] = 2 * t + 1;
#pragma unroll
        for (int e = 0; e < E_NUM; e++) atomicAdd(&s_imp[e], p[e]);
        atomicAdd(&s_load[e1], 1);
    }
    __syncthreads();
    if (tid < E_NUM) {
        atomicAdd(&g_imp[tid], s_imp[tid]);
        atomicAdd(&g_loadc[tid], s_load[tid]);
    }
}

// ---------------- convert x -> bf16 hi/lo ----------------
__global__ void __launch_bounds__(256) convert_x_kernel(const float* __restrict__ x) {
    size_t i = (size_t)blockIdx.x * 256 + threadIdx.x;
    float4 v = ((const float4*)x)[i];
    float f[4] = {v.x, v.y, v.z, v.w};
    __nv_bfloat16 h[4], l[4];
#pragma unroll
    for (int j = 0; j < 4; j++) {
        h[j] = __float2bfloat16(f[j]);
        l[j] = __float2bfloat16(f[j] - __bfloat162float(h[j]));
    }
    ((uint2*)g_x_hi)[i] = *(uint2*)&h[0];
    ((uint2*)g_x_lo)[i] = *(uint2*)&l[0];
}

// ---------------- convert + transpose weights ----------------
template <int K, int N, bool IS_W1>
__global__ void __launch_bounds__(256) convert_w_kernel(const float* __restrict__ W) {
    __shared__ float tile[32][33];
    int e  = blockIdx.z;
    int n0 = blockIdx.x * 32;
    int k0 = blockIdx.y * 32;
    int tx = threadIdx.x & 31, ty = threadIdx.x >> 5;
    const float* Wb = W + (size_t)e * K * N;
#pragma unroll
    for (int i = 0; i < 4; i++) {
        int k = k0 + ty * 4 + i;
        tile[ty * 4 + i][tx] = Wb[(size_t)k * N + n0 + tx];
    }
    __syncthreads();
    __nv_bfloat16* th = (IS_W1 ? g_w1t_hi : g_w2t_hi) + (size_t)e * N * K;
    __nv_bfloat16* tl = (IS_W1 ? g_w1t_lo : g_w2t_lo) + (size_t)e * N * K;
#pragma unroll
    for (int i = 0; i < 4; i++) {
        int n = n0 + ty * 4 + i;
        float v = tile[tx][ty * 4 + i];
        __nv_bfloat16 h = __float2bfloat16(v);
        __nv_bfloat16 l = __float2bfloat16(v - __bfloat162float(h));
        th[(size_t)n * K + k0 + tx] = h;
        tl[(size_t)n * K + k0 + tx] = l;
    }
}

// ---------------- mma.sync grouped GEMM ----------------
// Tile 128x128, K-chunk 64 (128B rows, SW128 swizzle), double-buffered cp.async.
// 8 warps: 2 (m) x 4 (n); warp tile 64x32. Split bf16: hi*hi + hi*lo + lo*hi.
template <int N_TOT, int K_SIZE, bool PHASE1>
__global__ void __launch_bounds__(256) gemm_tc(const float* __restrict__ bias) {
    int e   = blockIdx.z;
    int cnt = g_cnt[e];
    int m0  = blockIdx.y * 128;
    if (m0 >= cnt) return;
    int n0  = blockIdx.x * 128;

    extern __shared__ char smem[];
    uint32_t sb = smem_u32(smem);
    const int BUFSZ = 65536;
    const int AHI = 0, ALO = 16384, BHI = 32768, BLO = 49152;

    __shared__ int   sSlot[128];
    __shared__ float sBias[128];

    int tid  = threadIdx.x;
    int lane = tid & 31;
    int w    = tid >> 5;
    int wm   = w >> 2;     // 0..1
    int wn   = w & 3;      // 0..3

    if (tid < 128) {
        int m = m0 + tid;
        sSlot[tid] = (m < cnt) ? g_slots[e * CAP + m] : -1;
        sBias[tid] = bias[(size_t)e * N_TOT + n0 + tid];
    }
    __syncthreads();

    // global pointers for the 4 rows this thread loads per tile
    const __nv_bfloat16* Ah = PHASE1 ? g_x_hi   : g_h_hi;
    const __nv_bfloat16* Al = PHASE1 ? g_x_lo   : g_h_lo;
    const __nv_bfloat16* Bh = PHASE1 ? g_w1t_hi : g_w2t_hi;
    const __nv_bfloat16* Bl = PHASE1 ? g_w1t_lo : g_w2t_lo;

    const char* aHp[4]; const char* aLp[4];
    const char* bHp[4]; const char* bLp[4];
    bool aval[4];
    uint32_t dsw[4];
    int colB = (tid & 7) * 16;
#pragma unroll
    for (int j = 0; j < 4; j++) {
        int row = (tid >> 3) + j * 32;
        int s   = sSlot[row];
        aval[j] = (s >= 0);
        size_t arow = 0;
        if (aval[j]) arow = PHASE1 ? (size_t)(s >> 1) : (size_t)s;
        aHp[j] = (const char*)(Ah + arow * K_SIZE) + colB;
        aLp[j] = (const char*)(Al + arow * K_SIZE) + colB;
        size_t nrow = (size_t)e * N_TOT + n0 + row;
        bHp[j] = (const char*)(Bh + nrow * K_SIZE) + colB;
        bLp[j] = (const char*)(Bl + nrow * K_SIZE) + colB;
        uint32_t off = (uint32_t)row * 128 + colB;
        dsw[j] = off ^ ((off >> 3) & 0x70);
    }

#define LOAD_CHUNK(c) do { \
        uint32_t base_ = sb + ((c) & 1) * BUFSZ; \
        size_t kb_ = (size_t)(c) * 128; \
        _Pragma("unroll") \
        for (int j = 0; j < 4; j++) { \
            if (aval[j]) { \
                cp_async16(base_ + AHI + dsw[j], aHp[j] + kb_); \
                cp_async16(base_ + ALO + dsw[j], aLp[j] + kb_); \
            } \
            cp_async16(base_ + BHI + dsw[j], bHp[j] + kb_); \
            cp_async16(base_ + BLO + dsw[j], bLp[j] + kb_); \
        } \
    } while (0)

    // ldmatrix lane addressing: row = base_row + ((lane>>3)&1)*8 + (lane&7),
    // kbyte = base_kb + (lane>>4)*16, then SW128 swizzle.
    int lrow = ((lane >> 3) & 1) * 8 + (lane & 7);
    int lkb  = (lane >> 4) * 16;

    float acc[4][4][4];
#pragma unroll
    for (int i = 0; i < 4; i++)
#pragma unroll
        for (int j = 0; j < 4; j++)
#pragma unroll
            for (int q = 0; q < 4; q++) acc[i][j][q] = 0.f;

    constexpr int C = K_SIZE / 64;
    LOAD_CHUNK(0); CP_COMMIT();
    LOAD_CHUNK(1); CP_COMMIT();

    for (int c = 0; c < C; c++) {
        uint32_t base = sb + (c & 1) * BUFSZ;
        CP_WAIT1();
        __syncthreads();

#pragma unroll
        for (int kk = 0; kk < 4; kk++) {
            int kb = kk * 32 + lkb;
            uint32_t ah[4][4], al[4][4];
#pragma unroll
            for (int mi = 0; mi < 4; mi++) {
                uint32_t off = (uint32_t)(wm * 64 + mi * 16 + lrow) * 128 + kb;
                uint32_t sw  = off ^ ((off >> 3) & 0x70);
                ldmatrix_x4(ah[mi], base + AHI + sw);
                ldmatrix_x4(al[mi], base + ALO + sw);
            }
            uint32_t bh[2][4], bl[2][4];
#pragma unroll
            for (int ng = 0; ng < 2; ng++) {
                uint32_t off = (uint32_t)(wn * 32 + ng * 16 + lrow) * 128 + kb;
                uint32_t sw  = off ^ ((off >> 3) & 0x70);
                ldmatrix_x4(bh[ng], base + BHI + sw);
                ldmatrix_x4(bl[ng], base + BLO + sw);
            }
            // b-frag for n8 j within group ng: regs (r[j], r[j+2])
#pragma unroll
            for (int mi = 0; mi < 4; mi++) {
#pragma unroll
                for (int ng = 0; ng < 2; ng++) {
#pragma unroll
                    for (int jj = 0; jj < 2; jj++) {
                        int nj = ng * 2 + jj;
                        mma_16816(acc[mi][nj], ah[mi], bh[ng][jj], bh[ng][jj + 2]);
                        mma_16816(acc[mi][nj], ah[mi], bl[ng][jj], bl[ng][jj + 2]);
                        mma_16816(acc[mi][nj], al[mi], bh[ng][jj], bh[ng][jj + 2]);
                    }
                }
            }
        }

        __syncthreads();
        if (c + 2 < C) LOAD_CHUNK(c + 2);
        CP_COMMIT();
    }
#undef LOAD_CHUNK

    // ---------------- epilogue ----------------
#pragma unroll
    for (int mi = 0; mi < 4; mi++) {
#pragma unroll
        for (int h = 0; h < 2; h++) {
            int rloc = wm * 64 + mi * 16 + h * 8 + (lane >> 2);
            int slot = sSlot[rloc];
            if (slot < 0) continue;
#pragma unroll
            for (int nj = 0; nj < 4; nj++) {
                int cl = wn * 32 + nj * 8 + (lane & 3) * 2;
                float v0 = acc[mi][nj][h * 2 + 0] + sBias[cl];
                float v1 = acc[mi][nj][h * 2 + 1] + sBias[cl + 1];
                if (PHASE1) {
                    v0 = fmaxf(v0, 0.f);
                    v1 = fmaxf(v1, 0.f);
                    __nv_bfloat16 h0 = __float2bfloat16(v0);
                    __nv_bfloat16 h1 = __float2bfloat16(v1);
                    __nv_bfloat16 l0 = __float2bfloat16(v0 - __bfloat162float(h0));
                    __nv_bfloat16 l1 = __float2bfloat16(v1 - __bfloat162float(h1));
                    size_t bo = (size_t)slot * H_DIM + n0 + cl;
                    __nv_bfloat162 hp; hp.x = h0; hp.y = h1;
                    __nv_bfloat162 lp; lp.x = l0; lp.y = l1;
                    *(__nv_bfloat162*)&g_h_hi[bo] = hp;
                    *(__nv_bfloat162*)&g_h_lo[bo] = lp;
                } else {
                    size_t bo = (size_t)slot * D_DIM + n0 + cl;
                    float2 o; o.x = v0; o.y = v1;
                    *(float2*)&g_o[bo] = o;
                }
            }
        }
    }
}

// ---------------- combine + aux ----------------
__global__ void combine_kernel(float* __restrict__ y, long long out_size) {
    long long idx = (long long)blockIdx.x * blockDim.x + threadIdx.x;
    const long long BTD = (long long)BT * D_DIM;
    if (idx < BTD) {
        long long t = idx / D_DIM;
        long long d = idx - t * D_DIM;
        float r = g_gp[2 * t]     * g_o[(size_t)(2 * t) * D_DIM + d]
                + g_gp[2 * t + 1] * g_o[(size_t)(2 * t + 1) * D_DIM + d];
        y[idx] = r;
    } else if (idx < out_size) {
        float aux = 0.f;
        const float invBT = 1.f / (float)BT;
#pragma unroll
        for (int e = 0; e < E_NUM; e++)
            aux += (g_imp[e] * invBT) * ((float)g_loadc[e] * invBT);
        aux *= (float)E_NUM * 0.01f;
        y[idx] = aux;
    }
}

// ---------------- launch ----------------
extern "C" void kernel_launch(void* const* d_in, const int* in_sizes, int n_in,
                              void* d_out, int out_size) {
    const float* x  = (const float*)d_in[0];
    const float* gW = (const float*)d_in[1];
    const float* w1 = (const float*)d_in[2];
    const float* b1 = (const float*)d_in[3];
    const float* w2 = (const float*)d_in[4];
    const float* b2 = (const float*)d_in[5];
    float* out = (float*)d_out;

    const int SMEM_BYTES = 2 * 65536;   // 128 KB dynamic
    cudaFuncSetAttribute(gemm_tc<H_DIM, D_DIM, true>,
                         cudaFuncAttributeMaxDynamicSharedMemorySize, SMEM_BYTES);
    cudaFuncSetAttribute(gemm_tc<D_DIM, H_DIM, false>,
                         cudaFuncAttributeMaxDynamicSharedMemorySize, SMEM_BYTES);

    init_kernel<<<1, 32>>>();
    router_kernel<<<BT / 8, 256>>>(x, gW);
    convert_x_kernel<<<(BT * D_DIM / 4) / 256, 256>>>(x);
    convert_w_kernel<D_DIM, H_DIM, true ><<<dim3(H_DIM / 32, D_DIM / 32, E_NUM), 256>>>(w1);
    convert_w_kernel<H_DIM, D_DIM, false><<<dim3(D_DIM / 32, H_DIM / 32, E_NUM), 256>>>(w2);

    gemm_tc<H_DIM, D_DIM, true ><<<dim3(H_DIM / 128, CAP / 128, E_NUM), 256, SMEM_BYTES>>>(b1);
    gemm_tc<D_DIM, H_DIM, false><<<dim3(D_DIM / 128, CAP / 128, E_NUM), 256, SMEM_BYTES>>>(b2);

    long long total = out_size;
    int blocks = (int)((total + 255) / 256);
    combine_kernel<<<blocks, 256>>>(out, total);
}

// round 4
// speedup vs baseline: 3.9637x; 1.5220x over previous
#include <cuda_runtime.h>
#include <cuda_fp16.h>
#include <math.h>
#include <stdint.h>

#define BT      8192
#define D_DIM   1024
#define E_NUM   8
#define H_DIM   4096
#define CAP     (2*BT)
#define NSLOT   (2*BT)

// ---------------- device scratch ----------------
__device__ __half g_x[(size_t)BT * D_DIM];                       // A of GEMM1 (single fp16)
__device__ __half g_w1t_hi[(size_t)E_NUM * H_DIM * D_DIM];
__device__ __half g_w1t_lo[(size_t)E_NUM * H_DIM * D_DIM];
__device__ __half g_w2t_hi[(size_t)E_NUM * D_DIM * H_DIM];
__device__ __half g_w2t_lo[(size_t)E_NUM * D_DIM * H_DIM];
__device__ __half g_h[(size_t)NSLOT * H_DIM];                    // A of GEMM2 (single fp16)
__device__ float g_o[(size_t)NSLOT * D_DIM];
__device__ int   g_slots[E_NUM * CAP];
__device__ float g_gp[NSLOT];
__device__ int   g_cnt[E_NUM];
__device__ float g_imp[E_NUM];
__device__ int   g_loadc[E_NUM];

// ---------------- PTX helpers ----------------
__device__ __forceinline__ uint32_t smem_u32(const void* p) {
    return (uint32_t)__cvta_generic_to_shared(p);
}
__device__ __forceinline__ void cp_async16(uint32_t dst, const void* src) {
    asm volatile("cp.async.cg.shared.global [%0], [%1], 16;" :: "r"(dst), "l"(src));
}
#define CP_COMMIT() asm volatile("cp.async.commit_group;" ::: "memory")
#define CP_WAIT2()  asm volatile("cp.async.wait_group 2;" ::: "memory")

__device__ __forceinline__ void ldmatrix_x4(uint32_t* r, uint32_t addr) {
    asm volatile("ldmatrix.sync.aligned.m8n8.x4.shared.b16 {%0,%1,%2,%3}, [%4];"
        : "=r"(r[0]), "=r"(r[1]), "=r"(r[2]), "=r"(r[3]) : "r"(addr));
}
__device__ __forceinline__ void mma_16816(float* d, const uint32_t* a,
                                          uint32_t b0, uint32_t b1) {
    asm volatile(
        "mma.sync.aligned.m16n8k16.row.col.f32.f16.f16.f32 "
        "{%0,%1,%2,%3}, {%4,%5,%6,%7}, {%8,%9}, {%0,%1,%2,%3};"
        : "+f"(d[0]), "+f"(d[1]), "+f"(d[2]), "+f"(d[3])
        : "r"(a[0]), "r"(a[1]), "r"(a[2]), "r"(a[3]), "r"(b0), "r"(b1));
}

// ---------------- init ----------------
__global__ void init_kernel() {
    int i = threadIdx.x;
    if (i < E_NUM) { g_cnt[i] = 0; g_imp[i] = 0.f; g_loadc[i] = 0; }
}

// ---------------- router ----------------
__global__ void __launch_bounds__(256) router_kernel(const float* __restrict__ x,
                                                     const float* __restrict__ gW) {
    __shared__ float sW[E_NUM][D_DIM];
    __shared__ float s_imp[E_NUM];
    __shared__ int   s_load[E_NUM];
    int tid = threadIdx.x;
    if (tid < E_NUM) { s_imp[tid] = 0.f; s_load[tid] = 0; }
    for (int i = tid; i < D_DIM * E_NUM; i += 256) {
        int d = i / E_NUM, e = i % E_NUM;
        sW[e][d] = gW[i];
    }
    __syncthreads();

    int warp = tid >> 5, lane = tid & 31;
    int t = blockIdx.x * 8 + warp;
    const float* xr = x + (size_t)t * D_DIM;

    float acc[E_NUM];
#pragma unroll
    for (int e = 0; e < E_NUM; e++) acc[e] = 0.f;
    for (int d = lane; d < D_DIM; d += 32) {
        float xv = xr[d];
#pragma unroll
        for (int e = 0; e < E_NUM; e++) acc[e] = fmaf(xv, sW[e][d], acc[e]);
    }
#pragma unroll
    for (int off = 16; off > 0; off >>= 1) {
#pragma unroll
        for (int e = 0; e < E_NUM; e++)
            acc[e] += __shfl_xor_sync(0xffffffffu, acc[e], off);
    }

    if (lane == 0) {
        float mx = acc[0];
#pragma unroll
        for (int e = 1; e < E_NUM; e++) mx = fmaxf(mx, acc[e]);
        float p[E_NUM], s = 0.f;
#pragma unroll
        for (int e = 0; e < E_NUM; e++) { p[e] = expf(acc[e] - mx); s += p[e]; }
        float inv = 1.f / s;
#pragma unroll
        for (int e = 0; e < E_NUM; e++) p[e] *= inv;

        int e1 = 0; float v1 = p[0];
#pragma unroll
        for (int e = 1; e < E_NUM; e++) if (p[e] > v1) { v1 = p[e]; e1 = e; }
        int e2 = -1; float v2 = -1.f;
#pragma unroll
        for (int e = 0; e < E_NUM; e++) if (e != e1 && p[e] > v2) { v2 = p[e]; e2 = e; }

        float ginv = 1.f / (v1 + v2);
        g_gp[2 * t]     = v1 * ginv;
        g_gp[2 * t + 1] = v2 * ginv;

        int p1 = atomicAdd(&g_cnt[e1], 1); g_slots[e1 * CAP + p1] = 2 * t;
        int p2 = atomicAdd(&g_cnt[e2], 1); g_slots[e2 * CAP + p2] = 2 * t + 1;
#pragma unroll
        for (int e = 0; e < E_NUM; e++) atomicAdd(&s_imp[e], p[e]);
        atomicAdd(&s_load[e1], 1);
    }
    __syncthreads();
    if (tid < E_NUM) {
        atomicAdd(&g_imp[tid], s_imp[tid]);
        atomicAdd(&g_loadc[tid], s_load[tid]);
    }
}

// ---------------- convert x -> fp16 ----------------
__global__ void __launch_bounds__(256) convert_x_kernel(const float* __restrict__ x) {
    size_t i = (size_t)blockIdx.x * 256 + threadIdx.x;
    float4 v = ((const float4*)x)[i];
    float f[4] = {v.x, v.y, v.z, v.w};
    __half h[4];
#pragma unroll
    for (int j = 0; j < 4; j++) h[j] = __float2half_rn(f[j]);
    ((uint2*)g_x)[i] = *(uint2*)&h[0];
}

// ---------------- convert + transpose weights (fp16 hi/lo, vectorized writes) ----------------
// W: (E, K, N) fp32 -> Wt hi/lo: (E, N, K) fp16
template <int K, int N, bool IS_W1>
__global__ void __launch_bounds__(256) convert_w_kernel(const float* __restrict__ W) {
    __shared__ float tile[32][33];
    int e  = blockIdx.z;
    int n0 = blockIdx.x * 32;
    int k0 = blockIdx.y * 32;
    int t  = threadIdx.x;
    const float* Wb = W + (size_t)e * K * N;
#pragma unroll
    for (int j = 0; j < 4; j++) {
        int i = t + 256 * j;
        int k = i >> 5, n = i & 31;
        tile[k][n] = Wb[(size_t)(k0 + k) * N + n0 + n];
    }
    __syncthreads();
    __half* th = (IS_W1 ? g_w1t_hi : g_w2t_hi) + (size_t)e * N * K;
    __half* tl = (IS_W1 ? g_w1t_lo : g_w2t_lo) + (size_t)e * N * K;
    int nn = t >> 3;
    int kc = (t & 7) * 4;
    __half h[4], l[4];
#pragma unroll
    for (int q = 0; q < 4; q++) {
        float v = tile[kc + q][nn];
        h[q] = __float2half_rn(v);
        l[q] = __float2half_rn(v - __half2float(h[q]));
    }
    size_t o = (size_t)(n0 + nn) * K + k0 + kc;
    *(uint2*)&th[o] = *(uint2*)&h[0];
    *(uint2*)&tl[o] = *(uint2*)&l[0];
}

// ---------------- mma.sync grouped GEMM ----------------
// Tile 128x128, K-chunk 64 (128B rows, SW128 swizzle), 3-stage cp.async pipeline.
// 8 warps 2(m)x4(n), warp tile 64x32. A single fp16; B split hi/lo -> 2 MMAs.
template <int N_TOT, int K_SIZE, bool PHASE1>
__global__ void __launch_bounds__(256) gemm_tc(const float* __restrict__ bias) {
    int e   = blockIdx.z;
    int cnt = g_cnt[e];
    int m0  = blockIdx.y * 128;
    if (m0 >= cnt) return;
    int n0  = blockIdx.x * 128;

    extern __shared__ char smem[];
    uint32_t sb = smem_u32(smem);
    const int STAGE = 49152;
    const int AOF = 0, BHI = 16384, BLO = 32768;

    __shared__ int   sSlot[128];
    __shared__ float sBias[128];

    int tid  = threadIdx.x;
    int lane = tid & 31;
    int w    = tid >> 5;
    int wm   = w >> 2;
    int wn   = w & 3;

    if (tid < 128) {
        int m = m0 + tid;
        sSlot[tid] = (m < cnt) ? g_slots[e * CAP + m] : -1;
        sBias[tid] = bias[(size_t)e * N_TOT + n0 + tid];
    }
    __syncthreads();

    // zero A areas of all stages if ragged m-tile
    if (cnt - m0 < 128) {
#pragma unroll
        for (int s = 0; s < 3; s++) {
            uint32_t base = sb + s * STAGE + AOF;
            for (int off = tid * 16; off < 16384; off += 256 * 16)
                asm volatile("st.shared.v4.b32 [%0], {%1,%1,%1,%1};" :: "r"(base + off), "r"(0) : "memory");
        }
        __syncthreads();
    }

    const __half* Ap = PHASE1 ? g_x      : g_h;
    const __half* Bh = PHASE1 ? g_w1t_hi : g_w2t_hi;
    const __half* Bl = PHASE1 ? g_w1t_lo : g_w2t_lo;

    const char* aP[4];
    const char* bHp[4]; const char* bLp[4];
    bool aval[4];
    uint32_t dsw[4];
    int colB = (tid & 7) * 16;
#pragma unroll
    for (int j = 0; j < 4; j++) {
        int row = (tid >> 3) + j * 32;
        int s   = sSlot[row];
        aval[j] = (s >= 0);
        size_t arow = 0;
        if (aval[j]) arow = PHASE1 ? (size_t)(s >> 1) : (size_t)s;
        aP[j] = (const char*)(Ap + arow * K_SIZE) + colB;
        size_t nrow = (size_t)e * N_TOT + n0 + row;
        bHp[j] = (const char*)(Bh + nrow * K_SIZE) + colB;
        bLp[j] = (const char*)(Bl + nrow * K_SIZE) + colB;
        uint32_t off = (uint32_t)row * 128 + colB;
        dsw[j] = off ^ ((off >> 3) & 0x70);
    }

#define LOAD_CHUNK(c) do { \
        uint32_t base_ = sb + ((c) % 3) * STAGE; \
        size_t kb_ = (size_t)(c) * 128; \
        _Pragma("unroll") \
        for (int j = 0; j < 4; j++) { \
            if (aval[j]) cp_async16(base_ + AOF + dsw[j], aP[j] + kb_); \
            cp_async16(base_ + BHI + dsw[j], bHp[j] + kb_); \
            cp_async16(base_ + BLO + dsw[j], bLp[j] + kb_); \
        } \
    } while (0)

    int lrow = ((lane >> 3) & 1) * 8 + (lane & 7);
    int lkb  = (lane >> 4) * 16;

    float acc[4][4][4];
#pragma unroll
    for (int i = 0; i < 4; i++)
#pragma unroll
        for (int j = 0; j < 4; j++)
#pragma unroll
            for (int q = 0; q < 4; q++) acc[i][j][q] = 0.f;

    constexpr int C = K_SIZE / 64;
    LOAD_CHUNK(0); CP_COMMIT();
    LOAD_CHUNK(1); CP_COMMIT();
    LOAD_CHUNK(2); CP_COMMIT();

    for (int c = 0; c < C; c++) {
        uint32_t base = sb + (c % 3) * STAGE;
        CP_WAIT2();
        __syncthreads();

#pragma unroll
        for (int kk = 0; kk < 4; kk++) {
            int kb = kk * 32 + lkb;
            uint32_t ah[4][4];
#pragma unroll
            for (int mi = 0; mi < 4; mi++) {
                uint32_t off = (uint32_t)(wm * 64 + mi * 16 + lrow) * 128 + kb;
                uint32_t sw  = off ^ ((off >> 3) & 0x70);
                ldmatrix_x4(ah[mi], base + AOF + sw);
            }
            uint32_t bh[2][4], bl[2][4];
#pragma unroll
            for (int ng = 0; ng < 2; ng++) {
                uint32_t off = (uint32_t)(wn * 32 + ng * 16 + lrow) * 128 + kb;
                uint32_t sw  = off ^ ((off >> 3) & 0x70);
                ldmatrix_x4(bh[ng], base + BHI + sw);
                ldmatrix_x4(bl[ng], base + BLO + sw);
            }
#pragma unroll
            for (int mi = 0; mi < 4; mi++) {
#pragma unroll
                for (int ng = 0; ng < 2; ng++) {
#pragma unroll
                    for (int jj = 0; jj < 2; jj++) {
                        int nj = ng * 2 + jj;
                        mma_16816(acc[mi][nj], ah[mi], bh[ng][jj], bh[ng][jj + 2]);
                        mma_16816(acc[mi][nj], ah[mi], bl[ng][jj], bl[ng][jj + 2]);
                    }
                }
            }
        }

        __syncthreads();
        if (c + 3 < C) LOAD_CHUNK(c + 3);
        CP_COMMIT();
    }
#undef LOAD_CHUNK

    // ---------------- epilogue ----------------
#pragma unroll
    for (int mi = 0; mi < 4; mi++) {
#pragma unroll
        for (int h2 = 0; h2 < 2; h2++) {
            int rloc = wm * 64 + mi * 16 + h2 * 8 + (lane >> 2);
            int slot = sSlot[rloc];
            if (slot < 0) continue;
#pragma unroll
            for (int nj = 0; nj < 4; nj++) {
                int cl = wn * 32 + nj * 8 + (lane & 3) * 2;
                float v0 = acc[mi][nj][h2 * 2 + 0] + sBias[cl];
                float v1 = acc[mi][nj][h2 * 2 + 1] + sBias[cl + 1];
                if (PHASE1) {
                    v0 = fmaxf(v0, 0.f);
                    v1 = fmaxf(v1, 0.f);
                    __half2 hp;
                    hp.x = __float2half_rn(v0);
                    hp.y = __float2half_rn(v1);
                    size_t bo = (size_t)slot * H_DIM + n0 + cl;
                    *(__half2*)&g_h[bo] = hp;
                } else {
                    size_t bo = (size_t)slot * D_DIM + n0 + cl;
                    float2 o; o.x = v0; o.y = v1;
                    *(float2*)&g_o[bo] = o;
                }
            }
        }
    }
}

// ---------------- combine + aux ----------------
__global__ void combine_kernel(float* __restrict__ y, long long out_size) {
    long long idx = (long long)blockIdx.x * blockDim.x + threadIdx.x;
    const long long BTD = (long long)BT * D_DIM;
    if (idx < BTD) {
        long long t = idx / D_DIM;
        long long d = idx - t * D_DIM;
        float r = g_gp[2 * t]     * g_o[(size_t)(2 * t) * D_DIM + d]
                + g_gp[2 * t + 1] * g_o[(size_t)(2 * t + 1) * D_DIM + d];
        y[idx] = r;
    } else if (idx < out_size) {
        float aux = 0.f;
        const float invBT = 1.f / (float)BT;
#pragma unroll
        for (int e = 0; e < E_NUM; e++)
            aux += (g_imp[e] * invBT) * ((float)g_loadc[e] * invBT);
        aux *= (float)E_NUM * 0.01f;
        y[idx] = aux;
    }
}

// ---------------- launch ----------------
extern "C" void kernel_launch(void* const* d_in, const int* in_sizes, int n_in,
                              void* d_out, int out_size) {
    const float* x  = (const float*)d_in[0];
    const float* gW = (const float*)d_in[1];
    const float* w1 = (const float*)d_in[2];
    const float* b1 = (const float*)d_in[3];
    const float* w2 = (const float*)d_in[4];
    const float* b2 = (const float*)d_in[5];
    float* out = (float*)d_out;

    const int SMEM_BYTES = 3 * 49152;   // 144 KB dynamic
    cudaFuncSetAttribute(gemm_tc<H_DIM, D_DIM, true>,
                         cudaFuncAttributeMaxDynamicSharedMemorySize, SMEM_BYTES);
    cudaFuncSetAttribute(gemm_tc<D_DIM, H_DIM, false>,
                         cudaFuncAttributeMaxDynamicSharedMemorySize, SMEM_BYTES);

    init_kernel<<<1, 32>>>();
    router_kernel<<<BT / 8, 256>>>(x, gW);
    convert_x_kernel<<<(BT * D_DIM / 4) / 256, 256>>>(x);
    convert_w_kernel<D_DIM, H_DIM, true ><<<dim3(H_DIM / 32, D_DIM / 32, E_NUM), 256>>>(w1);
    convert_w_kernel<H_DIM, D_DIM, false><<<dim3(D_DIM / 32, H_DIM / 32, E_NUM), 256>>>(w2);

    gemm_tc<H_DIM, D_DIM, true ><<<dim3(H_DIM / 128, CAP / 128, E_NUM), 256, SMEM_BYTES>>>(b1);
    gemm_tc<D_DIM, H_DIM, false><<<dim3(D_DIM / 128, CAP / 128, E_NUM), 256, SMEM_BYTES>>>(b2);

    long long total = out_size;
    int blocks = (int)((total + 255) / 256);
    combine_kernel<<<blocks, 256>>>(out, total);
}

// round 5
// speedup vs baseline: 6.5130x; 1.6432x over previous
#include <cuda_runtime.h>
#include <cuda_fp16.h>
#include <math.h>
#include <stdint.h>

#define BT      8192
#define D_DIM   1024
#define E_NUM   8
#define H_DIM   4096
#define CAP     (2*BT)
#define NSLOT   (2*BT)

// ---------------- device scratch ----------------
__device__ __half g_x[(size_t)BT * D_DIM];
__device__ __half g_w1t[(size_t)E_NUM * H_DIM * D_DIM];
__device__ __half g_w2t[(size_t)E_NUM * D_DIM * H_DIM];
__device__ __half g_h[(size_t)NSLOT * H_DIM];
__device__ float g_o[(size_t)NSLOT * D_DIM];
__device__ int   g_slots[E_NUM * CAP];
__device__ float g_gp[NSLOT];
__device__ int   g_cnt[E_NUM];
__device__ float g_imp[E_NUM];
__device__ int   g_loadc[E_NUM];

// ---------------- PTX helpers ----------------
__device__ __forceinline__ uint32_t smem_u32(const void* p) {
    return (uint32_t)__cvta_generic_to_shared(p);
}
__device__ __forceinline__ void cp_async16(uint32_t dst, const void* src) {
    asm volatile("cp.async.cg.shared.global [%0], [%1], 16;" :: "r"(dst), "l"(src));
}
#define CP_COMMIT() asm volatile("cp.async.commit_group;" ::: "memory")
#define CP_WAIT2()  asm volatile("cp.async.wait_group 2;" ::: "memory")

__device__ __forceinline__ void ldmatrix_x4(uint32_t* r, uint32_t addr) {
    asm volatile("ldmatrix.sync.aligned.m8n8.x4.shared.b16 {%0,%1,%2,%3}, [%4];"
        : "=r"(r[0]), "=r"(r[1]), "=r"(r[2]), "=r"(r[3]) : "r"(addr));
}
__device__ __forceinline__ void mma_16816(float* d, const uint32_t* a,
                                          uint32_t b0, uint32_t b1) {
    asm volatile(
        "mma.sync.aligned.m16n8k16.row.col.f32.f16.f16.f32 "
        "{%0,%1,%2,%3}, {%4,%5,%6,%7}, {%8,%9}, {%0,%1,%2,%3};"
        : "+f"(d[0]), "+f"(d[1]), "+f"(d[2]), "+f"(d[3])
        : "r"(a[0]), "r"(a[1]), "r"(a[2]), "r"(a[3]), "r"(b0), "r"(b1));
}

// ---------------- init ----------------
__global__ void init_kernel() {
    int i = threadIdx.x;
    if (i < E_NUM) { g_cnt[i] = 0; g_imp[i] = 0.f; g_loadc[i] = 0; }
}

// ---------------- router ----------------
__global__ void __launch_bounds__(256) router_kernel(const float* __restrict__ x,
                                                     const float* __restrict__ gW) {
    __shared__ float sW[E_NUM][D_DIM];
    __shared__ float s_imp[E_NUM];
    __shared__ int   s_load[E_NUM];
    int tid = threadIdx.x;
    if (tid < E_NUM) { s_imp[tid] = 0.f; s_load[tid] = 0; }
    for (int i = tid; i < D_DIM * E_NUM; i += 256) {
        int d = i / E_NUM, e = i % E_NUM;
        sW[e][d] = gW[i];
    }
    __syncthreads();

    int warp = tid >> 5, lane = tid & 31;
    int t = blockIdx.x * 8 + warp;
    const float* xr = x + (size_t)t * D_DIM;

    float acc[E_NUM];
#pragma unroll
    for (int e = 0; e < E_NUM; e++) acc[e] = 0.f;
    for (int d = lane; d < D_DIM; d += 32) {
        float xv = xr[d];
#pragma unroll
        for (int e = 0; e < E_NUM; e++) acc[e] = fmaf(xv, sW[e][d], acc[e]);
    }
#pragma unroll
    for (int off = 16; off > 0; off >>= 1) {
#pragma unroll
        for (int e = 0; e < E_NUM; e++)
            acc[e] += __shfl_xor_sync(0xffffffffu, acc[e], off);
    }

    if (lane == 0) {
        float mx = acc[0];
#pragma unroll
        for (int e = 1; e < E_NUM; e++) mx = fmaxf(mx, acc[e]);
        float p[E_NUM], s = 0.f;
#pragma unroll
        for (int e = 0; e < E_NUM; e++) { p[e] = expf(acc[e] - mx); s += p[e]; }
        float inv = 1.f / s;
#pragma unroll
        for (int e = 0; e < E_NUM; e++) p[e] *= inv;

        int e1 = 0; float v1 = p[0];
#pragma unroll
        for (int e = 1; e < E_NUM; e++) if (p[e] > v1) { v1 = p[e]; e1 = e; }
        int e2 = -1; float v2 = -1.f;
#pragma unroll
        for (int e = 0; e < E_NUM; e++) if (e != e1 && p[e] > v2) { v2 = p[e]; e2 = e; }

        float ginv = 1.f / (v1 + v2);
        g_gp[2 * t]     = v1 * ginv;
        g_gp[2 * t + 1] = v2 * ginv;

        int p1 = atomicAdd(&g_cnt[e1], 1); g_slots[e1 * CAP + p1] = 2 * t;
        int p2 = atomicAdd(&g_cnt[e2], 1); g_slots[e2 * CAP + p2] = 2 * t + 1;
#pragma unroll
        for (int e = 0; e < E_NUM; e++) atomicAdd(&s_imp[e], p[e]);
        atomicAdd(&s_load[e1], 1);
    }
    __syncthreads();
    if (tid < E_NUM) {
        atomicAdd(&g_imp[tid], s_imp[tid]);
        atomicAdd(&g_loadc[tid], s_load[tid]);
    }
}

// ---------------- convert x -> fp16 ----------------
__global__ void __launch_bounds__(256) convert_x_kernel(const float* __restrict__ x) {
    size_t i = (size_t)blockIdx.x * 256 + threadIdx.x;
    float4 v = ((const float4*)x)[i];
    float f[4] = {v.x, v.y, v.z, v.w};
    __half h[4];
#pragma unroll
    for (int j = 0; j < 4; j++) h[j] = __float2half_rn(f[j]);
    ((uint2*)g_x)[i] = *(uint2*)&h[0];
}

// ---------------- convert + transpose weights (single fp16) ----------------
// W: (E, K, N) fp32 -> Wt: (E, N, K) fp16
template <int K, int N, bool IS_W1>
__global__ void __launch_bounds__(256) convert_w_kernel(const float* __restrict__ W) {
    __shared__ float tile[32][33];
    int e  = blockIdx.z;
    int n0 = blockIdx.x * 32;
    int k0 = blockIdx.y * 32;
    int t  = threadIdx.x;
    const float* Wb = W + (size_t)e * K * N;
#pragma unroll
    for (int j = 0; j < 4; j++) {
        int i = t + 256 * j;
        int k = i >> 5, n = i & 31;
        tile[k][n] = Wb[(size_t)(k0 + k) * N + n0 + n];
    }
    __syncthreads();
    __half* th = (IS_W1 ? g_w1t : g_w2t) + (size_t)e * N * K;
    int nn = t >> 3;
    int kc = (t & 7) * 4;
    __half h[4];
#pragma unroll
    for (int q = 0; q < 4; q++) h[q] = __float2half_rn(tile[kc + q][nn]);
    size_t o = (size_t)(n0 + nn) * K + k0 + kc;
    *(uint2*)&th[o] = *(uint2*)&h[0];
}

// ---------------- mma.sync grouped GEMM ----------------
// Tile 128x128, K-chunk 64 (128B rows, SW128 swizzle), 4-stage cp.async pipeline.
// 8 warps 2(m)x4(n), warp tile 64x32. A and B single fp16 -> 1 MMA per tile.
template <int N_TOT, int K_SIZE, bool PHASE1>
__global__ void __launch_bounds__(256) gemm_tc(const float* __restrict__ bias) {
    int e   = blockIdx.z;
    int cnt = g_cnt[e];
    int m0  = blockIdx.y * 128;
    if (m0 >= cnt) return;
    int n0  = blockIdx.x * 128;

    extern __shared__ char smem[];
    uint32_t sb = smem_u32(smem);
    const int STAGE = 32768;
    const int AOF = 0, BOF = 16384;

    __shared__ int   sSlot[128];
    __shared__ float sBias[128];

    int tid  = threadIdx.x;
    int lane = tid & 31;
    int w    = tid >> 5;
    int wm   = w >> 2;
    int wn   = w & 3;

    if (tid < 128) {
        int m = m0 + tid;
        sSlot[tid] = (m < cnt) ? g_slots[e * CAP + m] : -1;
        sBias[tid] = bias[(size_t)e * N_TOT + n0 + tid];
    }
    __syncthreads();

    // zero A areas of all stages if ragged m-tile
    if (cnt - m0 < 128) {
#pragma unroll
        for (int s = 0; s < 4; s++) {
            uint32_t base = sb + s * STAGE + AOF;
            for (int off = tid * 16; off < 16384; off += 256 * 16)
                asm volatile("st.shared.v4.b32 [%0], {%1,%1,%1,%1};" :: "r"(base + off), "r"(0) : "memory");
        }
        __syncthreads();
    }

    const __half* Ap = PHASE1 ? g_x   : g_h;
    const __half* Bp = PHASE1 ? g_w1t : g_w2t;

    const char* aP[4];
    const char* bP[4];
    bool aval[4];
    uint32_t dsw[4];
    int colB = (tid & 7) * 16;
#pragma unroll
    for (int j = 0; j < 4; j++) {
        int row = (tid >> 3) + j * 32;
        int s   = sSlot[row];
        aval[j] = (s >= 0);
        size_t arow = 0;
        if (aval[j]) arow = PHASE1 ? (size_t)(s >> 1) : (size_t)s;
        aP[j] = (const char*)(Ap + arow * K_SIZE) + colB;
        size_t nrow = (size_t)e * N_TOT + n0 + row;
        bP[j] = (const char*)(Bp + nrow * K_SIZE) + colB;
        uint32_t off = (uint32_t)row * 128 + colB;
        dsw[j] = off ^ ((off >> 3) & 0x70);
    }

#define LOAD_CHUNK(c) do { \
        uint32_t base_ = sb + ((c) & 3) * STAGE; \
        size_t kb_ = (size_t)(c) * 128; \
        _Pragma("unroll") \
        for (int j = 0; j < 4; j++) { \
            if (aval[j]) cp_async16(base_ + AOF + dsw[j], aP[j] + kb_); \
            cp_async16(base_ + BOF + dsw[j], bP[j] + kb_); \
        } \
    } while (0)

    int lrow = ((lane >> 3) & 1) * 8 + (lane & 7);
    int lkb  = (lane >> 4) * 16;

    float acc[4][4][4];
#pragma unroll
    for (int i = 0; i < 4; i++)
#pragma unroll
        for (int j = 0; j < 4; j++)
#pragma unroll
            for (int q = 0; q < 4; q++) acc[i][j][q] = 0.f;

    constexpr int C = K_SIZE / 64;
    LOAD_CHUNK(0); CP_COMMIT();
    LOAD_CHUNK(1); CP_COMMIT();
    LOAD_CHUNK(2); CP_COMMIT();

    for (int c = 0; c < C; c++) {
        uint32_t base = sb + (c & 3) * STAGE;
        CP_WAIT2();
        __syncthreads();

#pragma unroll
        for (int kk = 0; kk < 4; kk++) {
            int kb = kk * 32 + lkb;
            uint32_t ah[4][4];
#pragma unroll
            for (int mi = 0; mi < 4; mi++) {
                uint32_t off = (uint32_t)(wm * 64 + mi * 16 + lrow) * 128 + kb;
                uint32_t sw  = off ^ ((off >> 3) & 0x70);
                ldmatrix_x4(ah[mi], base + AOF + sw);
            }
            uint32_t bh[2][4];
#pragma unroll
            for (int ng = 0; ng < 2; ng++) {
                uint32_t off = (uint32_t)(wn * 32 + ng * 16 + lrow) * 128 + kb;
                uint32_t sw  = off ^ ((off >> 3) & 0x70);
                ldmatrix_x4(bh[ng], base + BOF + sw);
            }
#pragma unroll
            for (int mi = 0; mi < 4; mi++) {
#pragma unroll
                for (int ng = 0; ng < 2; ng++) {
#pragma unroll
                    for (int jj = 0; jj < 2; jj++) {
                        int nj = ng * 2 + jj;
                        mma_16816(acc[mi][nj], ah[mi], bh[ng][jj], bh[ng][jj + 2]);
                    }
                }
            }
        }

        __syncthreads();
        if (c + 3 < C) LOAD_CHUNK(c + 3);
        CP_COMMIT();
    }
#undef LOAD_CHUNK

    // ---------------- epilogue ----------------
#pragma unroll
    for (int mi = 0; mi < 4; mi++) {
#pragma unroll
        for (int h2 = 0; h2 < 2; h2++) {
            int rloc = wm * 64 + mi * 16 + h2 * 8 + (lane >> 2);
            int slot = sSlot[rloc];
            if (slot < 0) continue;
#pragma unroll
            for (int nj = 0; nj < 4; nj++) {
                int cl = wn * 32 + nj * 8 + (lane & 3) * 2;
                float v0 = acc[mi][nj][h2 * 2 + 0] + sBias[cl];
                float v1 = acc[mi][nj][h2 * 2 + 1] + sBias[cl + 1];
                if (PHASE1) {
                    v0 = fmaxf(v0, 0.f);
                    v1 = fmaxf(v1, 0.f);
                    __half2 hp;
                    hp.x = __float2half_rn(v0);
                    hp.y = __float2half_rn(v1);
                    size_t bo = (size_t)slot * H_DIM + n0 + cl;
                    *(__half2*)&g_h[bo] = hp;
                } else {
                    size_t bo = (size_t)slot * D_DIM + n0 + cl;
                    float2 o; o.x = v0; o.y = v1;
                    *(float2*)&g_o[bo] = o;
                }
            }
        }
    }
}

// ---------------- combine + aux ----------------
__global__ void combine_kernel(float* __restrict__ y, long long out_size) {
    long long idx = (long long)blockIdx.x * blockDim.x + threadIdx.x;
    const long long BTD = (long long)BT * D_DIM;
    if (idx < BTD) {
        long long t = idx / D_DIM;
        long long d = idx - t * D_DIM;
        float r = g_gp[2 * t]     * g_o[(size_t)(2 * t) * D_DIM + d]
                + g_gp[2 * t + 1] * g_o[(size_t)(2 * t + 1) * D_DIM + d];
        y[idx] = r;
    } else if (idx < out_size) {
        float aux = 0.f;
        const float invBT = 1.f / (float)BT;
#pragma unroll
        for (int e = 0; e < E_NUM; e++)
            aux += (g_imp[e] * invBT) * ((float)g_loadc[e] * invBT);
        aux *= (float)E_NUM * 0.01f;
        y[idx] = aux;
    }
}

// ---------------- launch ----------------
extern "C" void kernel_launch(void* const* d_in, const int* in_sizes, int n_in,
                              void* d_out, int out_size) {
    const float* x  = (const float*)d_in[0];
    const float* gW = (const float*)d_in[1];
    const float* w1 = (const float*)d_in[2];
    const float* b1 = (const float*)d_in[3];
    const float* w2 = (const float*)d_in[4];
    const float* b2 = (const float*)d_in[5];
    float* out = (float*)d_out;

    const int SMEM_BYTES = 4 * 32768;   // 128 KB dynamic
    cudaFuncSetAttribute(gemm_tc<H_DIM, D_DIM, true>,
                         cudaFuncAttributeMaxDynamicSharedMemorySize, SMEM_BYTES);
    cudaFuncSetAttribute(gemm_tc<D_DIM, H_DIM, false>,
                         cudaFuncAttributeMaxDynamicSharedMemorySize, SMEM_BYTES);

    init_kernel<<<1, 32>>>();
    router_kernel<<<BT / 8, 256>>>(x, gW);
    convert_x_kernel<<<(BT * D_DIM / 4) / 256, 256>>>(x);
    convert_w_kernel<D_DIM, H_DIM, true ><<<dim3(H_DIM / 32, D_DIM / 32, E_NUM), 256>>>(w1);
    convert_w_kernel<H_DIM, D_DIM, false><<<dim3(D_DIM / 32, H_DIM / 32, E_NUM), 256>>>(w2);

    gemm_tc<H_DIM, D_DIM, true ><<<dim3(H_DIM / 128, CAP / 128, E_NUM), 256, SMEM_BYTES>>>(b1);
    gemm_tc<D_DIM, H_DIM, false><<<dim3(D_DIM / 128, CAP / 128, E_NUM), 256, SMEM_BYTES>>>(b2);

    long long total = out_size;
    int blocks = (int)((total + 255) / 256);
    combine_kernel<<<blocks, 256>>>(out, total);
}

// round 6
// speedup vs baseline: 7.1439x; 1.0969x over previous
#include <cuda_runtime.h>
#include <cuda_fp16.h>
#include <math.h>
#include <stdint.h>

#define BT      8192
#define D_DIM   1024
#define E_NUM   8
#define H_DIM   4096
#define CAP     (2*BT)
#define NSLOT   (2*BT)

// ---------------- device scratch ----------------
__device__ __half g_x[(size_t)BT * D_DIM];
__device__ __half g_w1t[(size_t)E_NUM * H_DIM * D_DIM];
__device__ __half g_w2t[(size_t)E_NUM * D_DIM * H_DIM];
__device__ __half g_h[(size_t)NSLOT * H_DIM];
__device__ float g_o[(size_t)NSLOT * D_DIM];
__device__ int   g_slots[E_NUM * CAP];
__device__ float g_gp[NSLOT];
__device__ int   g_cnt[E_NUM];
__device__ float g_imp[E_NUM];
__device__ int   g_loadc[E_NUM];

// ---------------- PTX helpers ----------------
__device__ __forceinline__ uint32_t smem_u32(const void* p) {
    return (uint32_t)__cvta_generic_to_shared(p);
}
__device__ __forceinline__ void cp_async16(uint32_t dst, const void* src) {
    asm volatile("cp.async.cg.shared.global [%0], [%1], 16;" :: "r"(dst), "l"(src));
}
#define CP_COMMIT() asm volatile("cp.async.commit_group;" ::: "memory")
#define CP_WAIT2()  asm volatile("cp.async.wait_group 2;" ::: "memory")

__device__ __forceinline__ void ldmatrix_x4(uint32_t* r, uint32_t addr) {
    asm volatile("ldmatrix.sync.aligned.m8n8.x4.shared.b16 {%0,%1,%2,%3}, [%4];"
        : "=r"(r[0]), "=r"(r[1]), "=r"(r[2]), "=r"(r[3]) : "r"(addr));
}
__device__ __forceinline__ void mma_16816(float* d, const uint32_t* a,
                                          uint32_t b0, uint32_t b1) {
    asm volatile(
        "mma.sync.aligned.m16n8k16.row.col.f32.f16.f16.f32 "
        "{%0,%1,%2,%3}, {%4,%5,%6,%7}, {%8,%9}, {%0,%1,%2,%3};"
        : "+f"(d[0]), "+f"(d[1]), "+f"(d[2]), "+f"(d[3])
        : "r"(a[0]), "r"(a[1]), "r"(a[2]), "r"(a[3]), "r"(b0), "r"(b1));
}

// ---------------- init ----------------
__global__ void init_kernel() {
    int i = threadIdx.x;
    if (i < E_NUM) { g_cnt[i] = 0; g_imp[i] = 0.f; g_loadc[i] = 0; }
}

// ---------------- router ----------------
__global__ void __launch_bounds__(256) router_kernel(const float* __restrict__ x,
                                                     const float* __restrict__ gW) {
    __shared__ float sW[E_NUM][D_DIM];
    __shared__ float s_imp[E_NUM];
    __shared__ int   s_load[E_NUM];
    int tid = threadIdx.x;
    if (tid < E_NUM) { s_imp[tid] = 0.f; s_load[tid] = 0; }
    for (int i = tid; i < D_DIM * E_NUM; i += 256) {
        int d = i / E_NUM, e = i % E_NUM;
        sW[e][d] = gW[i];
    }
    __syncthreads();

    int warp = tid >> 5, lane = tid & 31;
    int t = blockIdx.x * 8 + warp;
    const float* xr = x + (size_t)t * D_DIM;

    float acc[E_NUM];
#pragma unroll
    for (int e = 0; e < E_NUM; e++) acc[e] = 0.f;
    for (int d = lane; d < D_DIM; d += 32) {
        float xv = xr[d];
#pragma unroll
        for (int e = 0; e < E_NUM; e++) acc[e] = fmaf(xv, sW[e][d], acc[e]);
    }
#pragma unroll
    for (int off = 16; off > 0; off >>= 1) {
#pragma unroll
        for (int e = 0; e < E_NUM; e++)
            acc[e] += __shfl_xor_sync(0xffffffffu, acc[e], off);
    }

    if (lane == 0) {
        float mx = acc[0];
#pragma unroll
        for (int e = 1; e < E_NUM; e++) mx = fmaxf(mx, acc[e]);
        float p[E_NUM], s = 0.f;
#pragma unroll
        for (int e = 0; e < E_NUM; e++) { p[e] = expf(acc[e] - mx); s += p[e]; }
        float inv = 1.f / s;
#pragma unroll
        for (int e = 0; e < E_NUM; e++) p[e] *= inv;

        int e1 = 0; float v1 = p[0];
#pragma unroll
        for (int e = 1; e < E_NUM; e++) if (p[e] > v1) { v1 = p[e]; e1 = e; }
        int e2 = -1; float v2 = -1.f;
#pragma unroll
        for (int e = 0; e < E_NUM; e++) if (e != e1 && p[e] > v2) { v2 = p[e]; e2 = e; }

        float ginv = 1.f / (v1 + v2);
        g_gp[2 * t]     = v1 * ginv;
        g_gp[2 * t + 1] = v2 * ginv;

        int p1 = atomicAdd(&g_cnt[e1], 1); g_slots[e1 * CAP + p1] = 2 * t;
        int p2 = atomicAdd(&g_cnt[e2], 1); g_slots[e2 * CAP + p2] = 2 * t + 1;
#pragma unroll
        for (int e = 0; e < E_NUM; e++) atomicAdd(&s_imp[e], p[e]);
        atomicAdd(&s_load[e1], 1);
    }
    __syncthreads();
    if (tid < E_NUM) {
        atomicAdd(&g_imp[tid], s_imp[tid]);
        atomicAdd(&g_loadc[tid], s_load[tid]);
    }
}

// ---------------- convert x -> fp16 ----------------
__global__ void __launch_bounds__(256) convert_x_kernel(const float* __restrict__ x) {
    size_t i = (size_t)blockIdx.x * 256 + threadIdx.x;
    float4 v = ((const float4*)x)[i];
    float f[4] = {v.x, v.y, v.z, v.w};
    __half h[4];
#pragma unroll
    for (int j = 0; j < 4; j++) h[j] = __float2half_rn(f[j]);
    ((uint2*)g_x)[i] = *(uint2*)&h[0];
}

// ---------------- convert + transpose weights (single fp16) ----------------
template <int K, int N, bool IS_W1>
__global__ void __launch_bounds__(256) convert_w_kernel(const float* __restrict__ W) {
    __shared__ float tile[32][33];
    int e  = blockIdx.z;
    int n0 = blockIdx.x * 32;
    int k0 = blockIdx.y * 32;
    int t  = threadIdx.x;
    const float* Wb = W + (size_t)e * K * N;
#pragma unroll
    for (int j = 0; j < 4; j++) {
        int i = t + 256 * j;
        int k = i >> 5, n = i & 31;
        tile[k][n] = Wb[(size_t)(k0 + k) * N + n0 + n];
    }
    __syncthreads();
    __half* th = (IS_W1 ? g_w1t : g_w2t) + (size_t)e * N * K;
    int nn = t >> 3;
    int kc = (t & 7) * 4;
    __half h[4];
#pragma unroll
    for (int q = 0; q < 4; q++) h[q] = __float2half_rn(tile[kc + q][nn]);
    size_t o = (size_t)(n0 + nn) * K + k0 + kc;
    *(uint2*)&th[o] = *(uint2*)&h[0];
}

// ---------------- mma.sync grouped GEMM ----------------
// CTA tile 128x256, K-chunk 64, 4-stage cp.async, SW128 swizzle.
// 8 warps 2(m)x4(n); warp tile 64x64. Single sync per k-chunk.
template <int N_TOT, int K_SIZE, bool PHASE1>
__global__ void __launch_bounds__(256, 1) gemm_tc(const float* __restrict__ bias) {
    int e   = blockIdx.z;
    int cnt = g_cnt[e];
    int m0  = blockIdx.y * 128;
    if (m0 >= cnt) return;
    int n0  = blockIdx.x * 256;

    extern __shared__ char smem[];
    uint32_t sb = smem_u32(smem);
    const int STAGE = 49152;          // 16KB A + 32KB B
    const int AOF = 0, BOF = 16384;

    __shared__ int   sSlot[128];
    __shared__ float sBias[256];

    int tid  = threadIdx.x;
    int lane = tid & 31;
    int w    = tid >> 5;
    int wm   = w >> 2;     // 0..1
    int wn   = w & 3;      // 0..3

    if (tid < 128) {
        int m = m0 + tid;
        sSlot[tid] = (m < cnt) ? g_slots[e * CAP + m] : -1;
    }
    sBias[tid] = bias[(size_t)e * N_TOT + n0 + tid];
    __syncthreads();

    // zero A areas of all stages if ragged m-tile
    if (cnt - m0 < 128) {
#pragma unroll
        for (int s = 0; s < 4; s++) {
            uint32_t base = sb + s * STAGE + AOF;
            for (int off = tid * 16; off < 16384; off += 256 * 16)
                asm volatile("st.shared.v4.b32 [%0], {%1,%1,%1,%1};" :: "r"(base + off), "r"(0) : "memory");
        }
        __syncthreads();
    }

    const __half* Ap = PHASE1 ? g_x   : g_h;
    const __half* Bp = PHASE1 ? g_w1t : g_w2t;

    const char* aP[4];
    const char* bP[8];
    bool aval[4];
    uint32_t dswA[4], dswB[8];
    int colB = (tid & 7) * 16;
#pragma unroll
    for (int j = 0; j < 4; j++) {
        int row = (tid >> 3) + j * 32;
        int s   = sSlot[row];
        aval[j] = (s >= 0);
        size_t arow = 0;
        if (aval[j]) arow = PHASE1 ? (size_t)(s >> 1) : (size_t)s;
        aP[j] = (const char*)(Ap + arow * K_SIZE) + colB;
        uint32_t off = (uint32_t)row * 128 + colB;
        dswA[j] = off ^ ((off >> 3) & 0x70);
    }
#pragma unroll
    for (int j = 0; j < 8; j++) {
        int row = (tid >> 3) + j * 32;          // 0..255
        size_t nrow = (size_t)e * N_TOT + n0 + row;
        bP[j] = (const char*)(Bp + nrow * K_SIZE) + colB;
        uint32_t off = (uint32_t)row * 128 + colB;
        dswB[j] = off ^ ((off >> 3) & 0x70);
    }

#define LOAD_CHUNK(c) do { \
        uint32_t base_ = sb + ((c) & 3) * STAGE; \
        size_t kb_ = (size_t)(c) * 128; \
        _Pragma("unroll") \
        for (int j = 0; j < 4; j++) \
            if (aval[j]) cp_async16(base_ + AOF + dswA[j], aP[j] + kb_); \
        _Pragma("unroll") \
        for (int j = 0; j < 8; j++) \
            cp_async16(base_ + BOF + dswB[j], bP[j] + kb_); \
    } while (0)

    int lrow = ((lane >> 3) & 1) * 8 + (lane & 7);
    int lkb  = (lane >> 4) * 16;

    float acc[4][8][4];
#pragma unroll
    for (int i = 0; i < 4; i++)
#pragma unroll
        for (int j = 0; j < 8; j++)
#pragma unroll
            for (int q = 0; q < 4; q++) acc[i][j][q] = 0.f;

    constexpr int C = K_SIZE / 64;
    LOAD_CHUNK(0); CP_COMMIT();
    LOAD_CHUNK(1); CP_COMMIT();
    LOAD_CHUNK(2); CP_COMMIT();

    for (int c = 0; c < C; c++) {
        uint32_t base = sb + (c & 3) * STAGE;
        CP_WAIT2();
        __syncthreads();

#pragma unroll
        for (int kk = 0; kk < 4; kk++) {
            int kb = kk * 32 + lkb;
            uint32_t ah[4][4];
#pragma unroll
            for (int mi = 0; mi < 4; mi++) {
                uint32_t off = (uint32_t)(wm * 64 + mi * 16 + lrow) * 128 + kb;
                uint32_t sw  = off ^ ((off >> 3) & 0x70);
                ldmatrix_x4(ah[mi], base + AOF + sw);
            }
            uint32_t bh[4][4];
#pragma unroll
            for (int ng = 0; ng < 4; ng++) {
                uint32_t off = (uint32_t)(wn * 64 + ng * 16 + lrow) * 128 + kb;
                uint32_t sw  = off ^ ((off >> 3) & 0x70);
                ldmatrix_x4(bh[ng], base + BOF + sw);
            }
#pragma unroll
            for (int mi = 0; mi < 4; mi++) {
#pragma unroll
                for (int ng = 0; ng < 4; ng++) {
#pragma unroll
                    for (int jj = 0; jj < 2; jj++) {
                        int nj = ng * 2 + jj;
                        mma_16816(acc[mi][nj], ah[mi], bh[ng][jj], bh[ng][jj + 2]);
                    }
                }
            }
        }

        // single sync per chunk: stage (c+3)&3 == (c-1)&3 is free —
        // the barrier at top of this iter proved all warps finished chunk c-1.
        if (c + 3 < C) LOAD_CHUNK(c + 3);
        CP_COMMIT();
    }
#undef LOAD_CHUNK

    // ---------------- epilogue ----------------
#pragma unroll
    for (int mi = 0; mi < 4; mi++) {
#pragma unroll
        for (int h2 = 0; h2 < 2; h2++) {
            int rloc = wm * 64 + mi * 16 + h2 * 8 + (lane >> 2);
            int slot = sSlot[rloc];
            if (slot < 0) continue;
#pragma unroll
            for (int nj = 0; nj < 8; nj++) {
                int cl = wn * 64 + nj * 8 + (lane & 3) * 2;
                float v0 = acc[mi][nj][h2 * 2 + 0] + sBias[cl];
                float v1 = acc[mi][nj][h2 * 2 + 1] + sBias[cl + 1];
                if (PHASE1) {
                    v0 = fmaxf(v0, 0.f);
                    v1 = fmaxf(v1, 0.f);
                    __half2 hp;
                    hp.x = __float2half_rn(v0);
                    hp.y = __float2half_rn(v1);
                    size_t bo = (size_t)slot * H_DIM + n0 + cl;
                    *(__half2*)&g_h[bo] = hp;
                } else {
                    size_t bo = (size_t)slot * D_DIM + n0 + cl;
                    float2 o; o.x = v0; o.y = v1;
                    *(float2*)&g_o[bo] = o;
                }
            }
        }
    }
}

// ---------------- combine (vectorized) + aux ----------------
__global__ void __launch_bounds__(256) combine_kernel(float* __restrict__ y) {
    size_t i = (size_t)blockIdx.x * 256 + threadIdx.x;    // float4 index
    size_t t = i / (D_DIM / 4);
    float gp1 = g_gp[2 * t], gp2 = g_gp[2 * t + 1];
    float4 a = ((const float4*)g_o)[t * (D_DIM / 4) * 2 + (i % (D_DIM / 4))];
    float4 b = ((const float4*)g_o)[(t * 2 + 1) * (D_DIM / 4) + (i % (D_DIM / 4))];
    float4 r;
    r.x = gp1 * a.x + gp2 * b.x;
    r.y = gp1 * a.y + gp2 * b.y;
    r.z = gp1 * a.z + gp2 * b.z;
    r.w = gp1 * a.w + gp2 * b.w;
    ((float4*)y)[i] = r;
}

__global__ void aux_kernel(float* __restrict__ y, long long out_size) {
    if (threadIdx.x == 0) {
        float aux = 0.f;
        const float invBT = 1.f / (float)BT;
#pragma unroll
        for (int e = 0; e < E_NUM; e++)
            aux += (g_imp[e] * invBT) * ((float)g_loadc[e] * invBT);
        aux *= (float)E_NUM * 0.01f;
        y[out_size - 1] = aux;
    }
}

// ---------------- launch ----------------
extern "C" void kernel_launch(void* const* d_in, const int* in_sizes, int n_in,
                              void* d_out, int out_size) {
    const float* x  = (const float*)d_in[0];
    const float* gW = (const float*)d_in[1];
    const float* w1 = (const float*)d_in[2];
    const float* b1 = (const float*)d_in[3];
    const float* w2 = (const float*)d_in[4];
    const float* b2 = (const float*)d_in[5];
    float* out = (float*)d_out;

    const int SMEM_BYTES = 4 * 49152;   // 192 KB dynamic
    cudaFuncSetAttribute(gemm_tc<H_DIM, D_DIM, true>,
                         cudaFuncAttributeMaxDynamicSharedMemorySize, SMEM_BYTES);
    cudaFuncSetAttribute(gemm_tc<D_DIM, H_DIM, false>,
                         cudaFuncAttributeMaxDynamicSharedMemorySize, SMEM_BYTES);

    init_kernel<<<1, 32>>>();
    router_kernel<<<BT / 8, 256>>>(x, gW);
    convert_x_kernel<<<(BT * D_DIM / 4) / 256, 256>>>(x);
    convert_w_kernel<D_DIM, H_DIM, true ><<<dim3(H_DIM / 32, D_DIM / 32, E_NUM), 256>>>(w1);
    convert_w_kernel<H_DIM, D_DIM, false><<<dim3(D_DIM / 32, H_DIM / 32, E_NUM), 256>>>(w2);

    gemm_tc<H_DIM, D_DIM, true ><<<dim3(H_DIM / 256, CAP / 128, E_NUM), 256, SMEM_BYTES>>>(b1);
    gemm_tc<D_DIM, H_DIM, false><<<dim3(D_DIM / 256, CAP / 128, E_NUM), 256, SMEM_BYTES>>>(b2);

    combine_kernel<<<(BT * D_DIM / 4) / 256, 256>>>(out);
    aux_kernel<<<1, 32>>>(out, (long long)out_size);
}